// round 3
// baseline (speedup 1.0000x reference)
#include <cuda_runtime.h>

#define BATCH    512
#define SIZE_IN  1024
#define SIZE_OUT 256
#define NQ       16

#define BT       64                 // batch tile
#define ISPLIT   32                 // split-k over the feature dim
#define ICHUNK   (SIZE_IN / ISPLIT) // 32 features per CTA
#define NTHREADS 256

// out[b,o] = bias[o]  (atomic accumulation target)
__global__ void il_init_out(const float* __restrict__ bias, float* __restrict__ out) {
    int i = blockIdx.x * blockDim.x + threadIdx.x;
    if (i < BATCH * SIZE_OUT) out[i] = bias[i & (SIZE_OUT - 1)];
}

// One CTA: 64 batches x 32 features x all 256 outputs.
// Per feature i: stage the 16 candidate weight rows (16 KB) into SMEM,
// then every thread FMAs its (batch-subgroup x 4-output) accumulators.
__global__ __launch_bounds__(NTHREADS, 2)
void il_main(const float* __restrict__ x,
             const int* __restrict__ indices,   // JAX canonicalizes int64 -> int32
             const float* __restrict__ table,
             float* __restrict__ out) {
    const int btile = blockIdx.x;        // 0..7
    const int ic    = blockIdx.y;        // 0..ISPLIT-1
    const int b0    = btile * BT;
    const int i0    = ic * ICHUNK;
    const int t     = threadIdx.x;
    const int og    = t & 63;            // output group: columns og*4 .. og*4+3
    const int bg    = t >> 6;            // batch subgroup: batches bg*16 .. +15

    __shared__ float sW[NQ * SIZE_OUT];  // 16 KB: 16 rows x 256 outputs for current i
    __shared__ float sx[BT * ICHUNK];    // 8 KB
    __shared__ int   sq[BT * ICHUNK];    // 8 KB

    // Preload x and quantile indices for the whole (64 batch x 32 i) tile.
    // Each thread: one batch-row quarter, 8 consecutive i's (coalesced 32B).
    {
        const int bl  = t >> 2;          // 0..63
        const int ii0 = (t & 3) * 8;     // 0,8,16,24
        const float* xp = x       + (size_t)(b0 + bl) * SIZE_IN + i0 + ii0;
        const int*   qp = indices + (size_t)(b0 + bl) * SIZE_IN + i0 + ii0;
        #pragma unroll
        for (int k = 0; k < 8; k++) {
            sx[bl * ICHUNK + ii0 + k] = xp[k];
            sq[bl * ICHUNK + ii0 + k] = qp[k];
        }
    }

    float4 acc[16];
    #pragma unroll
    for (int k = 0; k < 16; k++) acc[k] = make_float4(0.f, 0.f, 0.f, 0.f);

    for (int ii = 0; ii < ICHUNK; ii++) {
        const int i = i0 + ii;

        // Barrier also orders the sx/sq preload on the first iteration,
        // and protects sW readers from the new stores afterwards.
        __syncthreads();

        // Stage the 16 candidate rows for feature i: 1024 float4s, 4 per thread.
        #pragma unroll
        for (int k = 0; k < 4; k++) {
            const int f = k * NTHREADS + t;   // float4 slot 0..1023
            const int q = f >> 6;             // row 0..15
            const int c = f & 63;             // float4 column 0..63
            const float4 w = *reinterpret_cast<const float4*>(
                table + (size_t)(q * SIZE_IN + i) * SIZE_OUT + c * 4);
            *reinterpret_cast<float4*>(sW + q * SIZE_OUT + c * 4) = w;
        }
        __syncthreads();

        #pragma unroll
        for (int bl = 0; bl < 16; bl++) {
            const int b  = bg * 16 + bl;                 // uniform per warp -> LDS broadcast
            const float xv = sx[b * ICHUNK + ii];
            const int   q  = sq[b * ICHUNK + ii];
            const float4 w = *reinterpret_cast<const float4*>(sW + q * SIZE_OUT + og * 4);
            acc[bl].x += xv * w.x;
            acc[bl].y += xv * w.y;
            acc[bl].z += xv * w.z;
            acc[bl].w += xv * w.w;
        }
    }

    // Combine split-k partials.
    #pragma unroll
    for (int bl = 0; bl < 16; bl++) {
        const int b = b0 + bg * 16 + bl;
        float* op = out + (size_t)b * SIZE_OUT + og * 4;
        atomicAdd(op + 0, acc[bl].x);
        atomicAdd(op + 1, acc[bl].y);
        atomicAdd(op + 2, acc[bl].z);
        atomicAdd(op + 3, acc[bl].w);
    }
}

extern "C" void kernel_launch(void* const* d_in, const int* in_sizes, int n_in,
                              void* d_out, int out_size) {
    const float* x       = (const float*)d_in[0];
    const int*   indices = (const int*)d_in[1];
    const float* table   = (const float*)d_in[2];
    const float* bias    = (const float*)d_in[3];
    float*       out     = (float*)d_out;

    il_init_out<<<(BATCH * SIZE_OUT + 255) / 256, 256>>>(bias, out);

    dim3 grid(BATCH / BT, ISPLIT);
    il_main<<<grid, NTHREADS>>>(x, indices, table, out);
}

// round 4
// speedup vs baseline: 1.2944x; 1.2944x over previous
#include <cuda_runtime.h>
#include <cstdint>

#define BATCH    512
#define SIZE_IN  1024
#define SIZE_OUT 256
#define NQ       16

#define BT       64                 // batch tile per CTA
#define ISPLIT   32                 // split-k over features
#define ICHUNK   (SIZE_IN / ISPLIT) // 32 features per CTA
#define NTHREADS 512

// out[b,o] = bias[o]  (atomic accumulation target)
__global__ void il_init_out(const float* __restrict__ bias, float* __restrict__ out) {
    int i = blockIdx.x * blockDim.x + threadIdx.x;
    if (i < BATCH * SIZE_OUT) out[i] = bias[i & (SIZE_OUT - 1)];
}

__device__ __forceinline__ void cp_async16(uint32_t saddr, const void* gptr) {
    asm volatile("cp.async.cg.shared.global [%0], [%1], 16;\n" :: "r"(saddr), "l"(gptr));
}
__device__ __forceinline__ void cp_commit() {
    asm volatile("cp.async.commit_group;\n" ::: "memory");
}
__device__ __forceinline__ void cp_wait0() {
    asm volatile("cp.async.wait_group 0;\n" ::: "memory");
}

// One CTA: 64 batches x 32 features x 256 outputs.
// Double-buffered 16KB weight stage (all 16 q-rows of current feature),
// filled by cp.async for feature ii+1 while computing feature ii.
__global__ __launch_bounds__(NTHREADS, 2)
void il_main(const float* __restrict__ x,
             const int* __restrict__ indices,   // JAX canonicalizes int64 -> int32
             const float* __restrict__ table,
             float* __restrict__ out) {
    const int b0 = blockIdx.x * BT;
    const int i0 = blockIdx.y * ICHUNK;
    const int t  = threadIdx.x;
    const int og = t & 63;            // output columns og*4 .. og*4+3
    const int bg = t >> 6;            // batches bg*8 .. bg*8+7

    __shared__ float  sW[2][NQ * SIZE_OUT];   // 2 x 16 KB weight stage
    __shared__ float2 sxq[BT][ICHUNK];        // 16 KB: {x, float-offset q*256}

    const uint32_t sW_u32 = (uint32_t)__cvta_generic_to_shared(&sW[0][0]);

    // Preload x and quantile offsets for the whole (64 x 32) tile. Each thread:
    // one batch row, 4 consecutive features (16B vectorized, coalesced).
    {
        const int bl  = t >> 3;          // 0..63
        const int ii0 = (t & 7) * 4;     // 0,4,...,28
        const float4 xv = *reinterpret_cast<const float4*>(
            x + (size_t)(b0 + bl) * SIZE_IN + i0 + ii0);
        const int4 qv = *reinterpret_cast<const int4*>(
            indices + (size_t)(b0 + bl) * SIZE_IN + i0 + ii0);
        sxq[bl][ii0 + 0] = make_float2(xv.x, __int_as_float(qv.x * SIZE_OUT));
        sxq[bl][ii0 + 1] = make_float2(xv.y, __int_as_float(qv.y * SIZE_OUT));
        sxq[bl][ii0 + 2] = make_float2(xv.z, __int_as_float(qv.z * SIZE_OUT));
        sxq[bl][ii0 + 3] = make_float2(xv.w, __int_as_float(qv.w * SIZE_OUT));
    }

    float4 acc[8];
    #pragma unroll
    for (int k = 0; k < 8; k++) acc[k] = make_float4(0.f, 0.f, 0.f, 0.f);

    // Prefetch feature i0 into buffer 0: 1024 float4 slots, 2 per thread.
    #pragma unroll
    for (int k = 0; k < 2; k++) {
        const int f = k * NTHREADS + t;   // 0..1023
        const int q = f >> 6;             // 0..15
        const int c = f & 63;             // float4 column
        cp_async16(sW_u32 + (uint32_t)(q * SIZE_OUT + c * 4) * 4u,
                   table + ((size_t)q * SIZE_IN + i0) * SIZE_OUT + c * 4);
    }
    cp_commit();

    for (int ii = 0; ii < ICHUNK; ii++) {
        cp_wait0();
        __syncthreads();   // buf[ii&1] visible to all; all done reading buf[(ii+1)&1]

        if (ii + 1 < ICHUNK) {
            const int buf = (ii + 1) & 1;
            #pragma unroll
            for (int k = 0; k < 2; k++) {
                const int f = k * NTHREADS + t;
                const int q = f >> 6;
                const int c = f & 63;
                cp_async16(sW_u32 + (uint32_t)(buf * NQ * SIZE_OUT + q * SIZE_OUT + c * 4) * 4u,
                           table + ((size_t)q * SIZE_IN + i0 + ii + 1) * SIZE_OUT + c * 4);
            }
            cp_commit();
        }

        const float* wbuf = sW[ii & 1];
        #pragma unroll
        for (int bl = 0; bl < 8; bl++) {
            const int b = bg * 8 + bl;                    // uniform per warp -> broadcast
            const float2 v = sxq[b][ii];                  // {x, offset}
            const int off = __float_as_int(v.y);          // q*256 floats
            const float4 w = *reinterpret_cast<const float4*>(wbuf + off + og * 4);
            acc[bl].x += v.x * w.x;
            acc[bl].y += v.x * w.y;
            acc[bl].z += v.x * w.z;
            acc[bl].w += v.x * w.w;
        }
    }

    // Combine split-k partials.
    #pragma unroll
    for (int bl = 0; bl < 8; bl++) {
        const int b = b0 + bg * 8 + bl;
        float* op = out + (size_t)b * SIZE_OUT + og * 4;
        atomicAdd(op + 0, acc[bl].x);
        atomicAdd(op + 1, acc[bl].y);
        atomicAdd(op + 2, acc[bl].z);
        atomicAdd(op + 3, acc[bl].w);
    }
}

extern "C" void kernel_launch(void* const* d_in, const int* in_sizes, int n_in,
                              void* d_out, int out_size) {
    const float* x       = (const float*)d_in[0];
    const int*   indices = (const int*)d_in[1];
    const float* table   = (const float*)d_in[2];
    const float* bias    = (const float*)d_in[3];
    float*       out     = (float*)d_out;

    il_init_out<<<(BATCH * SIZE_OUT + 255) / 256, 256>>>(bias, out);

    dim3 grid(BATCH / BT, ISPLIT);
    il_main<<<grid, NTHREADS>>>(x, indices, table, out);
}